// round 10
// baseline (speedup 1.0000x reference)
#include <cuda_runtime.h>
#include <cuda_fp16.h>
#include <math.h>

// Problem constants (fixed by the dataset)
#define NND   100000
#define NED   1600000
#define DD    128
#define SCAN_B 256
#define MAXSB  ((NND + SCAN_B - 1) / SCAN_B + 1)

// ---------------- device scratch (no allocations allowed) ----------------
__device__ __half g_zh[(size_t)NND * DD];    // z in fp16 (25.6 MB) for the gather
__device__ float  g_ssrc[NND];
__device__ float  g_sdst[NND];
__device__ float  g_wts[NED];                // unnormalized exp weights, CSR order
__device__ int    g_count[NND];
__device__ int    g_cursor[NND];
__device__ int    g_off[NND + 1];
__device__ int    g_srcs[NED];               // CSR: src node per slot
__device__ int    g_bsum[MAXSB];
__device__ int    g_bpre[MAXSB];

// ---------------- tensor-core GEMM: z = h @ W (fp16 MMA, fused epilogue) --
// CTA tile: 128(M) x 128(N) x 128(K, fully resident). 8 warps, warp tile 32x64.
#define LDA 136            // padded row stride in halves
#define SMEM_HALVES (128 * LDA)
#define GEMM_SMEM_BYTES (2 * SMEM_HALVES * 2)

__device__ __forceinline__ unsigned smem_u32(const void* p) {
    return (unsigned)__cvta_generic_to_shared(p);
}

__global__ __launch_bounds__(256, 2)
void gemm_kernel(const float* __restrict__ h, const float* __restrict__ W,
                 const float* __restrict__ attn, int n) {
    extern __shared__ __half smem[];
    __half* Ah = smem;                 // h tile (fp16), later reused as z tile
    __half* Bh = smem + SMEM_HALVES;   // W (fp16), k-major [k][n]

    int tid = threadIdx.x;
    int lane = tid & 31;
    int warp = tid >> 5;
    int block_row = blockIdx.x * 128;

    // ---- load h tile (128x128 fp32 -> fp16) ----
#pragma unroll
    for (int t = 0; t < 16; t++) {
        int idx = tid + t * 256;
        int r = idx >> 5;
        int c4 = idx & 31;
        int grow = block_row + r;
        float4 v = (grow < n) ? reinterpret_cast<const float4*>(h + (size_t)grow * DD)[c4]
                              : make_float4(0.f, 0.f, 0.f, 0.f);
        __half2 p0 = __floats2half2_rn(v.x, v.y);
        __half2 p1 = __floats2half2_rn(v.z, v.w);
        *reinterpret_cast<__half2*>(&Ah[r * LDA + c4 * 4])     = p0;
        *reinterpret_cast<__half2*>(&Ah[r * LDA + c4 * 4 + 2]) = p1;
    }
    // ---- load W (128x128 fp32 -> fp16), k-major ----
#pragma unroll
    for (int t = 0; t < 16; t++) {
        int idx = tid + t * 256;
        int r = idx >> 5;
        int c4 = idx & 31;
        float4 v = reinterpret_cast<const float4*>(W + (size_t)r * DD)[c4];
        __half2 p0 = __floats2half2_rn(v.x, v.y);
        __half2 p1 = __floats2half2_rn(v.z, v.w);
        *reinterpret_cast<__half2*>(&Bh[r * LDA + c4 * 4])     = p0;
        *reinterpret_cast<__half2*>(&Bh[r * LDA + c4 * 4 + 2]) = p1;
    }
    __syncthreads();

    // ---- MMA mainloop ----
    int wm = warp >> 1;
    int wn = warp & 1;
    float acc[2][8][4];
#pragma unroll
    for (int i = 0; i < 2; i++)
#pragma unroll
        for (int j = 0; j < 8; j++)
#pragma unroll
            for (int r = 0; r < 4; r++) acc[i][j][r] = 0.f;

#pragma unroll
    for (int ks = 0; ks < 8; ks++) {
        int k0 = ks * 16;
        unsigned af[2][4];
#pragma unroll
        for (int i = 0; i < 2; i++) {
            int r0 = wm * 32 + i * 16;
            int row = r0 + (lane & 15);
            int col = k0 + ((lane >> 4) << 3);
            unsigned addr = smem_u32(&Ah[row * LDA + col]);
            asm volatile("ldmatrix.sync.aligned.m8n8.x4.shared.b16 {%0,%1,%2,%3}, [%4];"
                         : "=r"(af[i][0]), "=r"(af[i][1]), "=r"(af[i][2]), "=r"(af[i][3])
                         : "r"(addr));
        }
        unsigned bf[8][2];
#pragma unroll
        for (int j = 0; j < 8; j++) {
            int krow = k0 + (lane & 15);
            int ncol = wn * 64 + j * 8;
            unsigned addr = smem_u32(&Bh[krow * LDA + ncol]);
            asm volatile("ldmatrix.sync.aligned.m8n8.x2.trans.shared.b16 {%0,%1}, [%2];"
                         : "=r"(bf[j][0]), "=r"(bf[j][1])
                         : "r"(addr));
        }
#pragma unroll
        for (int i = 0; i < 2; i++)
#pragma unroll
            for (int j = 0; j < 8; j++) {
                asm volatile(
                    "mma.sync.aligned.m16n8k16.row.col.f32.f16.f16.f32 "
                    "{%0,%1,%2,%3}, {%4,%5,%6,%7}, {%8,%9}, {%0,%1,%2,%3};"
                    : "+f"(acc[i][j][0]), "+f"(acc[i][j][1]),
                      "+f"(acc[i][j][2]), "+f"(acc[i][j][3])
                    : "r"(af[i][0]), "r"(af[i][1]), "r"(af[i][2]), "r"(af[i][3]),
                      "r"(bf[j][0]), "r"(bf[j][1]));
            }
    }
    __syncthreads();

    // ---- accumulators -> fp16 z tile in smem (reuse Ah) ----
#pragma unroll
    for (int i = 0; i < 2; i++) {
        int r0 = wm * 32 + i * 16 + (lane >> 2);
#pragma unroll
        for (int j = 0; j < 8; j++) {
            int col = wn * 64 + j * 8 + ((lane & 3) << 1);
            *reinterpret_cast<__half2*>(&Ah[r0 * LDA + col]) =
                __floats2half2_rn(acc[i][j][0], acc[i][j][1]);
            *reinterpret_cast<__half2*>(&Ah[(r0 + 8) * LDA + col]) =
                __floats2half2_rn(acc[i][j][2], acc[i][j][3]);
        }
    }
    __syncthreads();

    // ---- coalesced global z store ----
#pragma unroll
    for (int t = 0; t < 8; t++) {
        int idx = tid + t * 256;
        int r = idx >> 4;
        int seg = idx & 15;
        int grow = block_row + r;
        if (grow < n) {
            uint4 v = *reinterpret_cast<const uint4*>(&Ah[r * LDA + seg * 8]);
            reinterpret_cast<uint4*>(&g_zh[(size_t)grow * DD])[seg] = v;
        }
    }

    // ---- per-row attention dots (16 rows per warp) ----
    float4 a1 = reinterpret_cast<const float4*>(attn)[lane];
    float4 a2 = reinterpret_cast<const float4*>(attn + DD)[lane];
#pragma unroll
    for (int rr = 0; rr < 16; rr++) {
        int r = warp * 16 + rr;
        int grow = block_row + r;
        const __half2 z0 = *reinterpret_cast<const __half2*>(&Ah[r * LDA + lane * 4]);
        const __half2 z1 = *reinterpret_cast<const __half2*>(&Ah[r * LDA + lane * 4 + 2]);
        float2 f0 = __half22float2(z0);
        float2 f1 = __half22float2(z1);
        float s1 = f0.x * a1.x + f0.y * a1.y + f1.x * a1.z + f1.y * a1.w;
        float s2 = f0.x * a2.x + f0.y * a2.y + f1.x * a2.z + f1.y * a2.w;
#pragma unroll
        for (int o = 16; o; o >>= 1) {
            s1 += __shfl_xor_sync(0xffffffff, s1, o);
            s2 += __shfl_xor_sync(0xffffffff, s2, o);
        }
        if (lane == 0 && grow < n) {
            g_ssrc[grow] = s1;
            g_sdst[grow] = s2;
        }
    }
}

// ---------------- CSR build -----------------------------------------------
__global__ void zero_kernel(int n) {
    int i = blockIdx.x * blockDim.x + threadIdx.x;
    if (i < n) g_count[i] = 0;
}

// 4 edges per thread via int4 loads
__global__ void hist_kernel(const int* __restrict__ dst, int ne) {
    int i = blockIdx.x * blockDim.x + threadIdx.x;
    int base = i * 4;
    if (base + 3 < ne) {
        int4 d = *reinterpret_cast<const int4*>(dst + base);
        atomicAdd(&g_count[d.x], 1);
        atomicAdd(&g_count[d.y], 1);
        atomicAdd(&g_count[d.z], 1);
        atomicAdd(&g_count[d.w], 1);
    } else {
        for (int e = base; e < ne; e++) atomicAdd(&g_count[dst[e]], 1);
    }
}

__global__ __launch_bounds__(SCAN_B)
void blocksum_kernel(int n) {
    int b = blockIdx.x;
    int t = threadIdx.x;
    int i = b * SCAN_B + t;
    int v = (i < n) ? g_count[i] : 0;
#pragma unroll
    for (int o = 16; o; o >>= 1) v += __shfl_xor_sync(0xffffffff, v, o);
    __shared__ int ws[SCAN_B / 32];
    int lane = t & 31, w = t >> 5;
    if (lane == 0) ws[w] = v;
    __syncthreads();
    if (t == 0) {
        int s = 0;
#pragma unroll
        for (int k = 0; k < SCAN_B / 32; k++) s += ws[k];
        g_bsum[b] = s;
    }
}

__global__ __launch_bounds__(1024)
void bscan_kernel(int nb, int n) {
    __shared__ int s[1024];
    int t = threadIdx.x;
    int v = (t < nb) ? g_bsum[t] : 0;
    s[t] = v;
    __syncthreads();
    for (int o = 1; o < 1024; o <<= 1) {
        int x = (t >= o) ? s[t - o] : 0;
        __syncthreads();
        s[t] += x;
        __syncthreads();
    }
    if (t < nb) g_bpre[t] = s[t] - v;
    if (t == 1023) g_off[n] = s[1023];
}

__global__ __launch_bounds__(SCAN_B)
void scan_blocks_kernel(int n) {
    int b = blockIdx.x;
    int t = threadIdx.x;
    int i = b * SCAN_B + t;
    int v = (i < n) ? g_count[i] : 0;

    int lane = t & 31, w = t >> 5;
    int x = v;
#pragma unroll
    for (int o = 1; o < 32; o <<= 1) {
        int y = __shfl_up_sync(0xffffffff, x, o);
        if (lane >= o) x += y;
    }
    __shared__ int ws[SCAN_B / 32];
    if (lane == 31) ws[w] = x;
    __syncthreads();
    if (w == 0) {
        int s = (lane < SCAN_B / 32) ? ws[lane] : 0;
#pragma unroll
        for (int o = 1; o < SCAN_B / 32; o <<= 1) {
            int y = __shfl_up_sync(0xffffffff, s, o);
            if (lane >= o) s += y;
        }
        if (lane < SCAN_B / 32) ws[lane] = s;
    }
    __syncthreads();
    int excl = g_bpre[b] + x + (w ? ws[w - 1] : 0) - v;
    if (i < n) { g_off[i] = excl; g_cursor[i] = excl; }
}

// scatter + fused edge-weight computation:
// w = exp(leaky_relu(ssrc[src] + sdst[dst]))  (no max subtraction: |e| <~ 6,
// exp can't overflow fp32; alpha = w/sum(w) is mathematically identical)
__device__ __forceinline__ void scatter_one(int s, int d) {
    int pos = atomicAdd(&g_cursor[d], 1);
    float x = g_ssrc[s] + g_sdst[d];
    x = (x > 0.f) ? x : 0.01f * x;
    g_srcs[pos] = s;
    g_wts[pos] = __expf(x);
}

__global__ void scatter_kernel(const int* __restrict__ src,
                               const int* __restrict__ dst, int ne) {
    int i = blockIdx.x * blockDim.x + threadIdx.x;
    int base = i * 4;
    if (base + 3 < ne) {
        int4 s4 = *reinterpret_cast<const int4*>(src + base);
        int4 d4 = *reinterpret_cast<const int4*>(dst + base);
        scatter_one(s4.x, d4.x);
        scatter_one(s4.y, d4.y);
        scatter_one(s4.z, d4.z);
        scatter_one(s4.w, d4.w);
    } else {
        for (int e = base; e < ne; e++) scatter_one(src[e], dst[e]);
    }
}

// ---------------- aggregation: warp per dst node, single pass -------------
__global__ __launch_bounds__(256)
void aggregate_kernel(float* __restrict__ out, int n) {
    int warp = (blockIdx.x * blockDim.x + threadIdx.x) >> 5;
    int lane = threadIdx.x & 31;
    if (warp >= n) return;

    int start = g_off[warp];
    int end   = g_off[warp + 1];
    float4* orow = reinterpret_cast<float4*>(out + (size_t)warp * DD);

    if (start == end) {
        orow[lane] = make_float4(0.f, 0.f, 0.f, 0.f);
        return;
    }

    float denom = 0.f;
    float acc0 = 0.f, acc1 = 0.f, acc2 = 0.f, acc3 = 0.f;
#pragma unroll 4
    for (int j = start; j < end; j++) {
        int s  = g_srcs[j];          // broadcast (all lanes same addr)
        float w = g_wts[j];          // broadcast
        denom += w;
        const uint2 hv = reinterpret_cast<const uint2*>(g_zh + (size_t)s * DD)[lane];
        __half2 h0 = *reinterpret_cast<const __half2*>(&hv.x);
        __half2 h1 = *reinterpret_cast<const __half2*>(&hv.y);
        float2 f0 = __half22float2(h0);
        float2 f1 = __half22float2(h1);
        acc0 = fmaf(w, f0.x, acc0);
        acc1 = fmaf(w, f0.y, acc1);
        acc2 = fmaf(w, f1.x, acc2);
        acc3 = fmaf(w, f1.y, acc3);
    }
    float inv = 1.0f / denom;
    orow[lane] = make_float4(acc0 * inv, acc1 * inv, acc2 * inv, acc3 * inv);
}

// ---------------- launch ---------------------------------------------------
extern "C" void kernel_launch(void* const* d_in, const int* in_sizes, int n_in,
                              void* d_out, int out_size) {
    const float* h      = (const float*)d_in[0];
    const float* W      = (const float*)d_in[1];
    const float* attn_w = (const float*)d_in[2];
    const int*   esrc   = (const int*)d_in[3];
    const int*   edst   = (const int*)d_in[4];
    float* out = (float*)d_out;

    int n  = in_sizes[0] / DD;   // 100000
    int ne = in_sizes[3];        // 1600000
    int nb = (n + SCAN_B - 1) / SCAN_B;
    int ne4 = (ne + 3) / 4;      // threads for 4-edge kernels

    cudaFuncSetAttribute(gemm_kernel, cudaFuncAttributeMaxDynamicSharedMemorySize,
                         GEMM_SMEM_BYTES);

    // 1) z = h @ W (fp16 tensor cores, fused attention dots + fp16 z store)
    gemm_kernel<<<(n + 127) / 128, 256, GEMM_SMEM_BYTES>>>(h, W, attn_w, n);
    // 2) CSR build by dst (+ fused exp weights in scatter)
    zero_kernel<<<(n + 255) / 256, 256>>>(n);
    hist_kernel<<<(ne4 + 255) / 256, 256>>>(edst, ne);
    blocksum_kernel<<<nb, SCAN_B>>>(n);
    bscan_kernel<<<1, 1024>>>(nb, n);
    scan_blocks_kernel<<<nb, SCAN_B>>>(n);
    scatter_kernel<<<(ne4 + 255) / 256, 256>>>(esrc, edst, ne);
    // 3) weighted aggregation, warp per dst node (single pass, no max)
    aggregate_kernel<<<(n * 32 + 255) / 256, 256>>>(out, n);
}

// round 13
// speedup vs baseline: 1.4323x; 1.4323x over previous
#include <cuda_runtime.h>
#include <cuda_fp16.h>
#include <math.h>

// Problem constants (fixed by the dataset)
#define NND   100000
#define NED   1600000
#define DD    128
#define SCAN_B 256
#define MAXSB  ((NND + SCAN_B - 1) / SCAN_B + 1)

// ---------------- device scratch (no allocations allowed) ----------------
__device__ __half g_zh[(size_t)NND * DD];    // z in fp16 (25.6 MB) for the gather
__device__ float  g_ssrc[NND];
__device__ float  g_sdst[NND];
__device__ int    g_count[NND];
__device__ int    g_cursor[NND];
__device__ int    g_off[NND + 1];
__device__ int    g_srcs[NED];
__device__ int    g_bsum[MAXSB];
__device__ int    g_bpre[MAXSB];

// ---------------- tensor-core GEMM: z = h @ W (fp16 MMA, fused epilogue) --
// CTA tile: 128(M) x 128(N) x 128(K, fully resident). 8 warps, warp tile 32x64.
#define LDA 136            // padded row stride in halves
#define SMEM_HALVES (128 * LDA)
#define GEMM_SMEM_BYTES (2 * SMEM_HALVES * 2)

__device__ __forceinline__ unsigned smem_u32(const void* p) {
    return (unsigned)__cvta_generic_to_shared(p);
}

__global__ __launch_bounds__(256, 2)
void gemm_kernel(const float* __restrict__ h, const float* __restrict__ W,
                 const float* __restrict__ attn, int n) {
    extern __shared__ __half smem[];
    __half* Ah = smem;                 // h tile (fp16), later reused as z tile
    __half* Bh = smem + SMEM_HALVES;   // W (fp16), k-major [k][n]

    int tid = threadIdx.x;
    int lane = tid & 31;
    int warp = tid >> 5;
    int block_row = blockIdx.x * 128;

    // ---- load h tile (128x128 fp32 -> fp16) ----
#pragma unroll
    for (int t = 0; t < 16; t++) {
        int idx = tid + t * 256;
        int r = idx >> 5;
        int c4 = idx & 31;
        int grow = block_row + r;
        float4 v = (grow < n) ? reinterpret_cast<const float4*>(h + (size_t)grow * DD)[c4]
                              : make_float4(0.f, 0.f, 0.f, 0.f);
        __half2 p0 = __floats2half2_rn(v.x, v.y);
        __half2 p1 = __floats2half2_rn(v.z, v.w);
        *reinterpret_cast<__half2*>(&Ah[r * LDA + c4 * 4])     = p0;
        *reinterpret_cast<__half2*>(&Ah[r * LDA + c4 * 4 + 2]) = p1;
    }
    // ---- load W (128x128 fp32 -> fp16), k-major ----
#pragma unroll
    for (int t = 0; t < 16; t++) {
        int idx = tid + t * 256;
        int r = idx >> 5;
        int c4 = idx & 31;
        float4 v = reinterpret_cast<const float4*>(W + (size_t)r * DD)[c4];
        __half2 p0 = __floats2half2_rn(v.x, v.y);
        __half2 p1 = __floats2half2_rn(v.z, v.w);
        *reinterpret_cast<__half2*>(&Bh[r * LDA + c4 * 4])     = p0;
        *reinterpret_cast<__half2*>(&Bh[r * LDA + c4 * 4 + 2]) = p1;
    }
    __syncthreads();

    // ---- MMA mainloop ----
    int wm = warp >> 1;
    int wn = warp & 1;
    float acc[2][8][4];
#pragma unroll
    for (int i = 0; i < 2; i++)
#pragma unroll
        for (int j = 0; j < 8; j++)
#pragma unroll
            for (int r = 0; r < 4; r++) acc[i][j][r] = 0.f;

#pragma unroll
    for (int ks = 0; ks < 8; ks++) {
        int k0 = ks * 16;
        unsigned af[2][4];
#pragma unroll
        for (int i = 0; i < 2; i++) {
            int r0 = wm * 32 + i * 16;
            int row = r0 + (lane & 15);
            int col = k0 + ((lane >> 4) << 3);
            unsigned addr = smem_u32(&Ah[row * LDA + col]);
            asm volatile("ldmatrix.sync.aligned.m8n8.x4.shared.b16 {%0,%1,%2,%3}, [%4];"
                         : "=r"(af[i][0]), "=r"(af[i][1]), "=r"(af[i][2]), "=r"(af[i][3])
                         : "r"(addr));
        }
        unsigned bf[8][2];
#pragma unroll
        for (int j = 0; j < 8; j++) {
            int krow = k0 + (lane & 15);
            int ncol = wn * 64 + j * 8;
            unsigned addr = smem_u32(&Bh[krow * LDA + ncol]);
            asm volatile("ldmatrix.sync.aligned.m8n8.x2.trans.shared.b16 {%0,%1}, [%2];"
                         : "=r"(bf[j][0]), "=r"(bf[j][1])
                         : "r"(addr));
        }
#pragma unroll
        for (int i = 0; i < 2; i++)
#pragma unroll
            for (int j = 0; j < 8; j++) {
                asm volatile(
                    "mma.sync.aligned.m16n8k16.row.col.f32.f16.f16.f32 "
                    "{%0,%1,%2,%3}, {%4,%5,%6,%7}, {%8,%9}, {%0,%1,%2,%3};"
                    : "+f"(acc[i][j][0]), "+f"(acc[i][j][1]),
                      "+f"(acc[i][j][2]), "+f"(acc[i][j][3])
                    : "r"(af[i][0]), "r"(af[i][1]), "r"(af[i][2]), "r"(af[i][3]),
                      "r"(bf[j][0]), "r"(bf[j][1]));
            }
    }
    __syncthreads();

    // ---- accumulators -> fp16 z tile in smem (reuse Ah) ----
#pragma unroll
    for (int i = 0; i < 2; i++) {
        int r0 = wm * 32 + i * 16 + (lane >> 2);
#pragma unroll
        for (int j = 0; j < 8; j++) {
            int col = wn * 64 + j * 8 + ((lane & 3) << 1);
            *reinterpret_cast<__half2*>(&Ah[r0 * LDA + col]) =
                __floats2half2_rn(acc[i][j][0], acc[i][j][1]);
            *reinterpret_cast<__half2*>(&Ah[(r0 + 8) * LDA + col]) =
                __floats2half2_rn(acc[i][j][2], acc[i][j][3]);
        }
    }
    __syncthreads();

    // ---- coalesced global z store ----
#pragma unroll
    for (int t = 0; t < 8; t++) {
        int idx = tid + t * 256;
        int r = idx >> 4;
        int seg = idx & 15;
        int grow = block_row + r;
        if (grow < n) {
            uint4 v = *reinterpret_cast<const uint4*>(&Ah[r * LDA + seg * 8]);
            reinterpret_cast<uint4*>(&g_zh[(size_t)grow * DD])[seg] = v;
        }
    }

    // ---- per-row attention dots (16 rows per warp) ----
    float4 a1 = reinterpret_cast<const float4*>(attn)[lane];
    float4 a2 = reinterpret_cast<const float4*>(attn + DD)[lane];
#pragma unroll
    for (int rr = 0; rr < 16; rr++) {
        int r = warp * 16 + rr;
        int grow = block_row + r;
        const __half2 z0 = *reinterpret_cast<const __half2*>(&Ah[r * LDA + lane * 4]);
        const __half2 z1 = *reinterpret_cast<const __half2*>(&Ah[r * LDA + lane * 4 + 2]);
        float2 f0 = __half22float2(z0);
        float2 f1 = __half22float2(z1);
        float s1 = f0.x * a1.x + f0.y * a1.y + f1.x * a1.z + f1.y * a1.w;
        float s2 = f0.x * a2.x + f0.y * a2.y + f1.x * a2.z + f1.y * a2.w;
#pragma unroll
        for (int o = 16; o; o >>= 1) {
            s1 += __shfl_xor_sync(0xffffffff, s1, o);
            s2 += __shfl_xor_sync(0xffffffff, s2, o);
        }
        if (lane == 0 && grow < n) {
            g_ssrc[grow] = s1;
            g_sdst[grow] = s2;
        }
    }
}

// ---------------- CSR build (round-8 form: 1 edge per thread) -------------
__global__ void zero_kernel(int n) {
    int i = blockIdx.x * blockDim.x + threadIdx.x;
    if (i < n) g_count[i] = 0;
}

__global__ void hist_kernel(const int* __restrict__ dst, int ne) {
    int e = blockIdx.x * blockDim.x + threadIdx.x;
    if (e < ne) atomicAdd(&g_count[dst[e]], 1);
}

__global__ __launch_bounds__(SCAN_B)
void blocksum_kernel(int n) {
    int b = blockIdx.x;
    int t = threadIdx.x;
    int i = b * SCAN_B + t;
    int v = (i < n) ? g_count[i] : 0;
#pragma unroll
    for (int o = 16; o; o >>= 1) v += __shfl_xor_sync(0xffffffff, v, o);
    __shared__ int ws[SCAN_B / 32];
    int lane = t & 31, w = t >> 5;
    if (lane == 0) ws[w] = v;
    __syncthreads();
    if (t == 0) {
        int s = 0;
#pragma unroll
        for (int k = 0; k < SCAN_B / 32; k++) s += ws[k];
        g_bsum[b] = s;
    }
}

__global__ __launch_bounds__(1024)
void bscan_kernel(int nb, int n) {
    __shared__ int s[1024];
    int t = threadIdx.x;
    int v = (t < nb) ? g_bsum[t] : 0;
    s[t] = v;
    __syncthreads();
    for (int o = 1; o < 1024; o <<= 1) {
        int x = (t >= o) ? s[t - o] : 0;
        __syncthreads();
        s[t] += x;
        __syncthreads();
    }
    if (t < nb) g_bpre[t] = s[t] - v;
    if (t == 1023) g_off[n] = s[1023];
}

__global__ __launch_bounds__(SCAN_B)
void scan_blocks_kernel(int n) {
    int b = blockIdx.x;
    int t = threadIdx.x;
    int i = b * SCAN_B + t;
    int v = (i < n) ? g_count[i] : 0;

    int lane = t & 31, w = t >> 5;
    int x = v;
#pragma unroll
    for (int o = 1; o < 32; o <<= 1) {
        int y = __shfl_up_sync(0xffffffff, x, o);
        if (lane >= o) x += y;
    }
    __shared__ int ws[SCAN_B / 32];
    if (lane == 31) ws[w] = x;
    __syncthreads();
    if (w == 0) {
        int s = (lane < SCAN_B / 32) ? ws[lane] : 0;
#pragma unroll
        for (int o = 1; o < SCAN_B / 32; o <<= 1) {
            int y = __shfl_up_sync(0xffffffff, s, o);
            if (lane >= o) s += y;
        }
        if (lane < SCAN_B / 32) ws[lane] = s;
    }
    __syncthreads();
    int excl = g_bpre[b] + x + (w ? ws[w - 1] : 0) - v;
    if (i < n) { g_off[i] = excl; g_cursor[i] = excl; }
}

__global__ void scatter_kernel(const int* __restrict__ src,
                               const int* __restrict__ dst, int ne) {
    int e = blockIdx.x * blockDim.x + threadIdx.x;
    if (e < ne) {
        int pos = atomicAdd(&g_cursor[dst[e]], 1);
        g_srcs[pos] = src[e];
    }
}

// ---------------- aggregation: warp per dst node, single pass -------------
// No max subtraction: scores are z.a sums with |e| <~ 6, so exp() cannot
// overflow fp32 and alpha = exp(e)/sum(exp(e)) is mathematically identical.
__global__ __launch_bounds__(256)
void aggregate_kernel(float* __restrict__ out, int n) {
    int warp = (blockIdx.x * blockDim.x + threadIdx.x) >> 5;
    int lane = threadIdx.x & 31;
    if (warp >= n) return;

    int start = g_off[warp];
    int end   = g_off[warp + 1];
    float4* orow = reinterpret_cast<float4*>(out + (size_t)warp * DD);

    if (start == end) {
        orow[lane] = make_float4(0.f, 0.f, 0.f, 0.f);
        return;
    }

    float sd = g_sdst[warp];

    float denom = 0.f;
    float acc0 = 0.f, acc1 = 0.f, acc2 = 0.f, acc3 = 0.f;
#pragma unroll 4
    for (int j = start; j < end; j++) {
        int s = g_srcs[j];                 // broadcast
        float x = g_ssrc[s] + sd;          // broadcast random load
        x = (x > 0.f) ? x : 0.01f * x;
        float w = __expf(x);
        denom += w;
        const uint2 hv = reinterpret_cast<const uint2*>(g_zh + (size_t)s * DD)[lane];
        __half2 h0 = *reinterpret_cast<const __half2*>(&hv.x);
        __half2 h1 = *reinterpret_cast<const __half2*>(&hv.y);
        float2 f0 = __half22float2(h0);
        float2 f1 = __half22float2(h1);
        acc0 = fmaf(w, f0.x, acc0);
        acc1 = fmaf(w, f0.y, acc1);
        acc2 = fmaf(w, f1.x, acc2);
        acc3 = fmaf(w, f1.y, acc3);
    }
    float inv = 1.0f / denom;
    orow[lane] = make_float4(acc0 * inv, acc1 * inv, acc2 * inv, acc3 * inv);
}

// ---------------- launch ---------------------------------------------------
extern "C" void kernel_launch(void* const* d_in, const int* in_sizes, int n_in,
                              void* d_out, int out_size) {
    const float* h      = (const float*)d_in[0];
    const float* W      = (const float*)d_in[1];
    const float* attn_w = (const float*)d_in[2];
    const int*   esrc   = (const int*)d_in[3];
    const int*   edst   = (const int*)d_in[4];
    float* out = (float*)d_out;

    int n  = in_sizes[0] / DD;   // 100000
    int ne = in_sizes[3];        // 1600000
    int nb = (n + SCAN_B - 1) / SCAN_B;

    cudaFuncSetAttribute(gemm_kernel, cudaFuncAttributeMaxDynamicSharedMemorySize,
                         GEMM_SMEM_BYTES);

    // 1) z = h @ W (fp16 tensor cores, fused attention dots + fp16 z store)
    gemm_kernel<<<(n + 127) / 128, 256, GEMM_SMEM_BYTES>>>(h, W, attn_w, n);
    // 2) CSR build by dst
    zero_kernel<<<(n + 255) / 256, 256>>>(n);
    hist_kernel<<<(ne + 255) / 256, 256>>>(edst, ne);
    blocksum_kernel<<<nb, SCAN_B>>>(n);
    bscan_kernel<<<1, 1024>>>(nb, n);
    scan_blocks_kernel<<<nb, SCAN_B>>>(n);
    scatter_kernel<<<(ne + 255) / 256, 256>>>(esrc, edst, ne);
    // 3) weighted aggregation, warp per dst node (single pass, no max)
    aggregate_kernel<<<(n * 32 + 255) / 256, 256>>>(out, n);
}